// round 7
// baseline (speedup 1.0000x reference)
#include <cuda_runtime.h>
#include <cuda_bf16.h>
#include <cstdint>

#define BATCH 128
#define CH    128
#define NN    170
#define TT    12
#define NP    176          // padded node pitch (f32 words)
#define SCP   172          // score pitch (bf16)

static __device__ __align__(16) float g_xs[BATCH * CH * NP];  // t-reduced x
static __device__ __align__(16) float g_Ed[BATCH * NN * NP];  // E_d^T [b][m][n]
static __device__ float g_Asum[NN * NN];

// k_gemm1 smem: es bf16-pairs [128][88 u32] + xs f32 [128][88]
#define SMEM_G1 ((11264 + 11264) * 4)                  // 90,112 B -> 2 CTA/SM
// k_adj smem: ed f32 [170][176] + sc bf16 [170][172]
#define SMEM_A  (NN * NP * 4 + NN * SCP * 2)           // 178,160 B

// ------------------------------------------------------- packed f32x2 helpers
typedef unsigned long long u64t;

__device__ __forceinline__ u64t splat2(float v) {
    u64t d; asm("mov.b64 %0, {%1, %1};" : "=l"(d) : "f"(v)); return d;
}
__device__ __forceinline__ u64t splat2u(unsigned v) {     // f32 bits in u32
    u64t d; asm("mov.b64 %0, {%1, %1};" : "=l"(d) : "r"(v)); return d;
}
__device__ __forceinline__ void ffma2(u64t& c, u64t a, u64t b) {
    asm("fma.rn.f32x2 %0, %1, %2, %3;" : "=l"(c) : "l"(a), "l"(b), "l"(c));
}
__device__ __forceinline__ void unpack2(float& lo, float& hi, u64t v) {
    asm("mov.b64 {%0, %1}, %2;" : "=f"(lo), "=f"(hi) : "l"(v));
}
__device__ __forceinline__ float tanh_ap(float x) {
    float r; asm("tanh.approx.f32 %0, %1;" : "=f"(r) : "f"(x)); return r;
}

// ------------------------------------ K_load: streaming t-reduction x -> g_xs
__global__ void k_load(const float* __restrict__ x) {
    const int total = BATCH * CH * NP;
    for (int i = blockIdx.x * blockDim.x + threadIdx.x; i < total;
         i += gridDim.x * blockDim.x) {
        int np = i % NP;
        int bc = i / NP;
        float s = 0.0f;
        if (np < NN) {
            const float4* p = reinterpret_cast<const float4*>(
                x + ((size_t)bc * NN + np) * TT);
            float4 v0 = __ldcs(p), v1 = __ldcs(p + 1), v2 = __ldcs(p + 2);
            s = ((v0.x + v0.y) + (v0.z + v0.w))
              + ((v1.x + v1.y) + (v1.z + v1.w))
              + ((v2.x + v2.y) + (v2.z + v2.w));
        }
        g_xs[i] = s;
    }
}

// --------------- K_gemm1: ed[m][n] = tanh(sum_c Es[c][m] * xs[c][n])  (8x8)
// grid (128 batches, 2 n-halves), 256 threads, 242 cells of 8m x 8n each.
__global__ void __launch_bounds__(256, 2) k_gemm1(const float* __restrict__ Es) {
    extern __shared__ float smf[];
    unsigned* es = reinterpret_cast<unsigned*>(smf);   // bf16x2 [128][88]
    float* xs = smf + CH * 88;                         // f32 [128][88]
    const int tid = threadIdx.x;
    const int b = blockIdx.x, h = blockIdx.y;

    // stage Es as packed bf16 pairs (m-major pairs): es[c][mp] = {Es[c][2mp], Es[c][2mp+1]}
    for (int i = tid; i < CH * 88; i += 256) {
        int c = i / 88, mp = i - c * 88;
        int m0 = mp * 2;
        float f0 = 0.f, f1 = 0.f;
        if (m0 < NN) {
            float2 e = *reinterpret_cast<const float2*>(Es + c * NN + m0);
            f0 = e.x; f1 = e.y;
        }
        __nv_bfloat162 hh = __floats2bfloat162_rn(f0, f1);
        es[i] = *reinterpret_cast<unsigned*>(&hh);
    }
    // stage xs half (f32, from L2-resident g_xs), vectorized
    {
        const float* src = g_xs + (size_t)b * CH * NP + 88 * h;
        for (int i = tid; i < CH * 22; i += 256) {
            int c = i / 22, q = i - c * 22;
            reinterpret_cast<float4*>(xs)[c * 22 + q] =
                *reinterpret_cast<const float4*>(src + (size_t)c * NP + q * 4);
        }
    }
    __syncthreads();

    // 22 m-strips(8) x 11 n-strips(8) = 242 cells; ~1 per thread
    const int cell = tid;
    if (cell < 242) {
        const int smi = cell / 11, snj = cell - smi * 11;
        const int am = smi * 8, bn = snj * 8;
        u64t acc[8][4];
        #pragma unroll
        for (int i = 0; i < 8; i++)
            #pragma unroll
            for (int j = 0; j < 4; j++) acc[i][j] = 0ull;

        const unsigned* ep = es + (am >> 1);
        const float* bp = xs + bn;
        #pragma unroll 4
        for (int c = 0; c < CH; c++) {
            uint4 ev = *reinterpret_cast<const uint4*>(ep + c * 88);
            ulonglong2 b01 = *reinterpret_cast<const ulonglong2*>(bp + c * 88);
            ulonglong2 b23 = *reinterpret_cast<const ulonglong2*>(bp + c * 88 + 4);
            unsigned ew[4] = {ev.x, ev.y, ev.z, ev.w};
            #pragma unroll
            for (int q = 0; q < 4; q++) {
                u64t s0 = splat2u(ew[q] << 16);
                u64t s1 = splat2u(ew[q] & 0xFFFF0000u);
                ffma2(acc[2*q][0], s0, b01.x);  ffma2(acc[2*q][1], s0, b01.y);
                ffma2(acc[2*q][2], s0, b23.x);  ffma2(acc[2*q][3], s0, b23.y);
                ffma2(acc[2*q+1][0], s1, b01.x); ffma2(acc[2*q+1][1], s1, b01.y);
                ffma2(acc[2*q+1][2], s1, b23.x); ffma2(acc[2*q+1][3], s1, b23.y);
            }
        }

        // epilogue: tanh -> g_Ed[b][m][88h+bn .. +7]
        #pragma unroll
        for (int mi = 0; mi < 8; mi++) {
            int m = am + mi;
            if (m < NN) {
                float f[8];
                #pragma unroll
                for (int j = 0; j < 4; j++) unpack2(f[2*j], f[2*j+1], acc[mi][j]);
                float4 lo, hi;
                lo.x = tanh_ap(f[0]); lo.y = tanh_ap(f[1]);
                lo.z = tanh_ap(f[2]); lo.w = tanh_ap(f[3]);
                hi.x = tanh_ap(f[4]); hi.y = tanh_ap(f[5]);
                hi.z = tanh_ap(f[6]); hi.w = tanh_ap(f[7]);
                float* dst = g_Ed + ((size_t)b * NN + m) * NP + 88 * h + bn;
                *reinterpret_cast<float4*>(dst) = lo;
                *reinterpret_cast<float4*>(dst + 4) = hi;
            }
        }
    }
}

// ---------------- K_adj: symmetric GEMM2 (8x8 triangle blocks) + softmax + acc
__global__ void __launch_bounds__(512, 1) k_adj() {
    extern __shared__ float sm[];
    float* ed = sm;                                          // [170][176]
    __nv_bfloat16* sc = reinterpret_cast<__nv_bfloat16*>(sm + NN * NP);
    const int tid = threadIdx.x;
    const int b = blockIdx.x;

    // coalesced copy-in (already [m][n] layout, pads zero)
    {
        const uint4* src = reinterpret_cast<const uint4*>(g_Ed + (size_t)b * NN * NP);
        uint4* dst = reinterpret_cast<uint4*>(ed);
        for (int i = tid; i < (NN * NP) / 4; i += 512) dst[i] = src[i];
    }
    __syncthreads();

    // 22 strips of 8: triangle pairs (si >= sj) -> 253 blocks, 1 per thread
    const float scale = 0.08838834764831843f;                // 1/sqrt(128)
    const int cell = tid;
    if (cell < 253) {
        int si = (int)((sqrtf(8.0f * (float)cell + 1.0f) - 1.0f) * 0.5f);
        while ((si + 1) * (si + 2) / 2 <= cell) si++;
        while (si * (si + 1) / 2 > cell) si--;
        const int sj = cell - si * (si + 1) / 2;
        const int n = si * 8, k = sj * 8;

        u64t acc[8][4];                                      // [ki][n-pair]
        #pragma unroll
        for (int i = 0; i < 8; i++)
            #pragma unroll
            for (int j = 0; j < 4; j++) acc[i][j] = 0ull;

        #pragma unroll 2
        for (int m = 0; m < NN; m++) {
            const float* row = ed + m * NP;
            ulonglong2 a01 = *reinterpret_cast<const ulonglong2*>(row + n);
            ulonglong2 a23 = *reinterpret_cast<const ulonglong2*>(row + n + 4);
            float4 k0 = *reinterpret_cast<const float4*>(row + k);
            float4 k1 = *reinterpret_cast<const float4*>(row + k + 4);
            float kv[8] = {k0.x, k0.y, k0.z, k0.w, k1.x, k1.y, k1.z, k1.w};
            #pragma unroll
            for (int ki = 0; ki < 8; ki++) {
                u64t s = splat2(kv[ki]);
                ffma2(acc[ki][0], s, a01.x); ffma2(acc[ki][1], s, a01.y);
                ffma2(acc[ki][2], s, a23.x); ffma2(acc[ki][3], s, a23.y);
            }
        }

        // epilogue: relu/scale -> bf16 scores, write block + mirror
        #pragma unroll
        for (int ki = 0; ki < 8; ki++) {
            int kk = k + ki;
            if (kk >= NN) continue;
            #pragma unroll
            for (int j = 0; j < 4; j++) {
                float v0, v1;
                unpack2(v0, v1, acc[ki][j]);
                int n0 = n + 2 * j, n1 = n0 + 1;
                __nv_bfloat16 h0 = __float2bfloat16(fmaxf(0.0f, v0 * scale));
                __nv_bfloat16 h1 = __float2bfloat16(fmaxf(0.0f, v1 * scale));
                if (n0 < NN) { sc[n0 * SCP + kk] = h0; sc[kk * SCP + n0] = h0; }
                if (n1 < NN) { sc[n1 * SCP + kk] = h1; sc[kk * SCP + n1] = h1; }
            }
        }
    }
    __syncthreads();

    // row softmax (scores in [0,~15.1] -> no max pass) + atomic accumulate
    const int wid = tid >> 5, lane = tid & 31;
    for (int n = wid; n < NN; n += 16) {
        const __nv_bfloat16* row = sc + n * SCP;
        float ssum = 0.0f;
        for (int kq = lane; kq < NN; kq += 32)
            ssum += __expf(__bfloat162float(row[kq]));
        #pragma unroll
        for (int o = 16; o; o >>= 1)
            ssum += __shfl_xor_sync(0xffffffffu, ssum, o);
        float inv = 1.0f / ssum;
        for (int kq = lane; kq < NN; kq += 32)
            atomicAdd(&g_Asum[n * NN + kq],
                      __expf(__bfloat162float(row[kq])) * inv);
    }
}

// --------------------------------- K_thresh: threshold + self-restore g_Asum
__global__ void k_thresh(float* __restrict__ out) {
    int i = blockIdx.x * blockDim.x + threadIdx.x;
    if (i < NN * NN) {
        out[i] = (g_Asum[i] > 64.0f) ? 1.0f : 0.0f;          // mean > 0.5
        g_Asum[i] = 0.0f;                                    // restore for replay
    }
}

// ------------------------------------------------------------------- launcher
extern "C" void kernel_launch(void* const* d_in, const int* in_sizes, int n_in,
                              void* d_out, int out_size) {
    const float* x  = (const float*)d_in[0];   // [128,128,170,12] f32
    const float* Es = (const float*)d_in[1];   // [128,170] f32
    float* out = (float*)d_out;                // [170,170] f32

    cudaFuncSetAttribute(k_gemm1, cudaFuncAttributeMaxDynamicSharedMemorySize, SMEM_G1);
    cudaFuncSetAttribute(k_adj,   cudaFuncAttributeMaxDynamicSharedMemorySize, SMEM_A);

    k_load<<<592, 256>>>(x);
    dim3 g1(BATCH, 2);
    k_gemm1<<<g1, 256, SMEM_G1>>>(Es);
    k_adj<<<BATCH, 512, SMEM_A>>>();
    k_thresh<<<(NN * NN + 255) / 256, 256>>>(out);
}